// round 4
// baseline (speedup 1.0000x reference)
#include <cuda_runtime.h>
#include <math.h>

#define NB   8192
#define ND   256
#define NPOS 8
#define NT   64      // number of 128-wide column tiles

// ---------------- device scratch (no allocations allowed) ----------------
__device__ float g_z[NB * ND];          // normalized embeddings
__device__ float g_pSpd[NT * NB];       // per (colTile,row): sum e^s over pos+diag
__device__ float g_pSneg[NT * NB];      // per (colTile,row): sum e^s over neg
__device__ float g_pTneg[NT * NB];      // per (colTile,row): sum s*e^s over neg
__device__ float g_pos_s[NB * NPOS];    // s at positive pairs
__device__ float g_lse[NB];
__device__ float g_inv_temp;
__device__ unsigned g_negmin_e, g_negmax_e, g_pvmin_e, g_pvmax_e;

// monotone float<->uint encoding so atomicMin/Max on unsigned give float min/max
__device__ __forceinline__ unsigned encf(float f) {
    unsigned u = __float_as_uint(f);
    return (u & 0x80000000u) ? ~u : (u | 0x80000000u);
}
__device__ __forceinline__ float decf(unsigned e) {
    return __uint_as_float((e & 0x80000000u) ? (e & 0x7FFFFFFFu) | ((e >> 31) ? 0u : 0u) : 0u);
}
// (decf above is wrong-prone; use explicit inverse)
__device__ __forceinline__ float decf2(unsigned e) {
    unsigned u = (e & 0x80000000u) ? (e ^ 0x80000000u) : ~e;
    return __uint_as_float(u);
}

// ---------------- kernels ----------------
__global__ void k_init(const float* __restrict__ temp) {
    float t = temp[0];
    float sp = log1pf(expf(t));       // softplus
    g_inv_temp = 1.0f / sp;
    g_negmin_e = 0xFFFFFFFFu;
    g_negmax_e = 0u;
    g_pvmin_e  = 0xFFFFFFFFu;
    g_pvmax_e  = 0u;
}

__global__ void k_norm(const float* __restrict__ emb) {
    int row = blockIdx.x;
    int t   = threadIdx.x;                 // 256 threads, one element each
    float x = emb[row * ND + t];
    float s = x * x;
    #pragma unroll
    for (int o = 16; o > 0; o >>= 1) s += __shfl_xor_sync(0xFFFFFFFFu, s, o);
    __shared__ float ws[8];
    if ((t & 31) == 0) ws[t >> 5] = s;
    __syncthreads();
    float tot = 0.0f;
    #pragma unroll
    for (int i = 0; i < 8; i++) tot += ws[i];
    float norm = sqrtf(tot);
    float dn = fmaxf(norm, 1e-12f);
    g_z[row * ND + t] = x / dn;
}

__global__ void k_pvminmax(const float* __restrict__ pv) {
    int i = blockIdx.x * blockDim.x + threadIdx.x;    // 65536 total
    float v = pv[i];
    float mn = v, mx = v;
    #pragma unroll
    for (int o = 16; o > 0; o >>= 1) {
        mn = fminf(mn, __shfl_xor_sync(0xFFFFFFFFu, mn, o));
        mx = fmaxf(mx, __shfl_xor_sync(0xFFFFFFFFu, mx, o));
    }
    if ((threadIdx.x & 31) == 0) {
        atomicMin(&g_pvmin_e, encf(mn));
        atomicMax(&g_pvmax_e, encf(mx));
    }
}

// 128x128 tile of sim per block; fused exp + masked reductions epilogue.
__global__ void __launch_bounds__(256, 2) k_gemm() {
    const int bm = blockIdx.y, bn = blockIdx.x;
    const int tid = threadIdx.x;
    const int tx = tid & 15, ty = tid >> 4;
    const int row0 = bm * 128, col0 = bn * 128;

    __shared__ float As[8][132];
    __shared__ float Bs[8][132];

    float acc[8][8];
    #pragma unroll
    for (int i = 0; i < 8; i++)
        #pragma unroll
        for (int j = 0; j < 8; j++) acc[i][j] = 0.0f;

    const int lr = tid >> 1;          // row within tile this thread loads
    const int kh = (tid & 1) * 4;     // k-half offset

    for (int k0 = 0; k0 < ND; k0 += 8) {
        float4 a = *reinterpret_cast<const float4*>(&g_z[(row0 + lr) * ND + k0 + kh]);
        float4 b = *reinterpret_cast<const float4*>(&g_z[(col0 + lr) * ND + k0 + kh]);
        As[kh + 0][lr] = a.x; As[kh + 1][lr] = a.y; As[kh + 2][lr] = a.z; As[kh + 3][lr] = a.w;
        Bs[kh + 0][lr] = b.x; Bs[kh + 1][lr] = b.y; Bs[kh + 2][lr] = b.z; Bs[kh + 3][lr] = b.w;
        __syncthreads();
        #pragma unroll
        for (int kk = 0; kk < 8; kk++) {
            float ra[8], rb[8];
            #pragma unroll
            for (int i = 0; i < 8; i++) ra[i] = As[kk][ty * 8 + i];
            #pragma unroll
            for (int j = 0; j < 8; j++) rb[j] = Bs[kk][tx * 8 + j];
            #pragma unroll
            for (int i = 0; i < 8; i++)
                #pragma unroll
                for (int j = 0; j < 8; j++) acc[i][j] = fmaf(ra[i], rb[j], acc[i][j]);
        }
        __syncthreads();
    }

    // ---- epilogue: s = (dot-1)*inv_temp (shift-invariant, diag-dominant) ----
    const float it = g_inv_temp;
    float spd[8], sng[8], tng[8];
    #pragma unroll
    for (int i = 0; i < 8; i++) { spd[i] = 0.0f; sng[i] = 0.0f; tng[i] = 0.0f; }
    float lmin = 1e30f, lmax = -1e30f;

    #pragma unroll
    for (int i = 0; i < 8; i++) {
        int gi = row0 + ty * 8 + i;
        #pragma unroll
        for (int j = 0; j < 8; j++) {
            int gj = col0 + tx * 8 + j;
            float s = (acc[i][j] - 1.0f) * it;
            float e = __expf(s);
            int d = gj - gi;
            if (d < 0) d += NB;
            if (d == 0) {
                spd[i] += e;
            } else if (d <= NPOS) {
                spd[i] += e;
                g_pos_s[gi * NPOS + (d - 1)] = s;   // unique writer
            } else {
                sng[i] += e;
                tng[i] += s * e;
                lmin = fminf(lmin, s);
                lmax = fmaxf(lmax, s);
            }
        }
    }

    // reduce each row's partials across the 16 tx lanes (half-warp segments)
    #pragma unroll
    for (int i = 0; i < 8; i++) {
        float a0 = spd[i], a1 = sng[i], a2 = tng[i];
        #pragma unroll
        for (int o = 8; o > 0; o >>= 1) {
            a0 += __shfl_down_sync(0xFFFFFFFFu, a0, o, 16);
            a1 += __shfl_down_sync(0xFFFFFFFFu, a1, o, 16);
            a2 += __shfl_down_sync(0xFFFFFFFFu, a2, o, 16);
        }
        if (tx == 0) {
            int gi = row0 + ty * 8 + i;
            g_pSpd [bn * NB + gi] = a0;
            g_pSneg[bn * NB + gi] = a1;
            g_pTneg[bn * NB + gi] = a2;
        }
    }

    // global neg min/max via order-invariant encoded atomics
    #pragma unroll
    for (int o = 16; o > 0; o >>= 1) {
        lmin = fminf(lmin, __shfl_xor_sync(0xFFFFFFFFu, lmin, o));
        lmax = fmaxf(lmax, __shfl_xor_sync(0xFFFFFFFFu, lmax, o));
    }
    if ((tid & 31) == 0) {
        atomicMin(&g_negmin_e, encf(lmin));
        atomicMax(&g_negmax_e, encf(lmax));
    }
}

__global__ void k_lse() {
    int i = blockIdx.x * blockDim.x + threadIdx.x;   // 8192 rows
    float spd = 0.0f, sn = 0.0f, tn = 0.0f;
    #pragma unroll 8
    for (int t = 0; t < NT; t++) {
        spd += g_pSpd [t * NB + i];
        sn  += g_pSneg[t * NB + i];
        tn  += g_pTneg[t * NB + i];
    }
    float nmin = decf2(g_negmin_e);
    float nmax = decf2(g_negmax_e);
    float a = 1.0f / (nmax - nmin + 1e-8f);
    float b = 1.0f - nmin * a;
    g_lse[i] = logf(spd + a * tn + b * sn);
}

__global__ void k_final(const float* __restrict__ pv, float* __restrict__ out) {
    const int tid = threadIdx.x;                     // 1024 threads, 1 block
    float vmin = decf2(g_pvmin_e);
    float vmax = decf2(g_pvmax_e);
    float wmin = 1.0f - vmax;
    float wmax = 1.0f - vmin;
    float inv = 1.0f / (wmax - wmin + 1e-8f);

    float local = 0.0f;
    for (int idx = tid; idx < NB * NPOS; idx += 1024) {
        int i = idx >> 3;
        float pw = ((1.0f - pv[idx]) - wmin) * inv;
        local += (g_pos_s[idx] - g_lse[i]) * pw;
    }
    __shared__ float red[1024];
    red[tid] = local;
    __syncthreads();
    for (int s = 512; s > 0; s >>= 1) {
        if (tid < s) red[tid] += red[tid + s];
        __syncthreads();
    }
    if (tid == 0) out[0] = -red[0] * (1.0f / (float)(NB * NPOS));
}

// ---------------- launch ----------------
extern "C" void kernel_launch(void* const* d_in, const int* in_sizes, int n_in,
                              void* d_out, int out_size) {
    const float* emb  = (const float*)d_in[0];
    const float* pv   = (const float*)d_in[1];
    const float* temp = (const float*)d_in[2];
    float* out = (float*)d_out;

    k_init<<<1, 1>>>(temp);
    k_norm<<<NB, ND>>>(emb);
    k_pvminmax<<<(NB * NPOS) / 1024, 1024>>>(pv);
    dim3 grid(NT, NT);
    k_gemm<<<grid, 256>>>();
    k_lse<<<NB / 256, 256>>>();
    k_final<<<1, 1024>>>(pv, out);
}

// round 8
// speedup vs baseline: 3.2815x; 3.2815x over previous
#include <cuda_runtime.h>
#include <cuda_bf16.h>
#include <math.h>
#include <stdint.h>

#define NB 8192
#define ND 256
#define NPOS 8
#define RS 528           // smem row stride bytes (256 bf16 + 8 pad)
#define TILE_B (128 * RS)

__device__ __align__(16) __nv_bfloat16 g_zb[NB * ND];
__device__ float g_pSpd[4 * NB], g_pSneg[4 * NB], g_pTneg[4 * NB];
__device__ float g_pos_s[NB * NPOS], g_lse[NB];
__device__ float g_it;
__device__ unsigned g_negmin_e, g_negmax_e, g_pvmin_e, g_pvmax_e;

__device__ __forceinline__ unsigned encf(float f) {
    unsigned u = __float_as_uint(f);
    return (u & 0x80000000u) ? ~u : (u | 0x80000000u);
}
__device__ __forceinline__ float decf2(unsigned e) {
    unsigned u = (e & 0x80000000u) ? (e ^ 0x80000000u) : ~e;
    return __uint_as_float(u);
}

#define CP16(s, g)  asm volatile("cp.async.cg.shared.global [%0], [%1], 16;" :: "r"(s), "l"(g))
#define CP_COMMIT() asm volatile("cp.async.commit_group;" ::: "memory")
#define CP_WAIT(n)  asm volatile("cp.async.wait_group %0;" :: "n"(n) : "memory")

__device__ __forceinline__ uint32_t smem_u32(const void* p) {
    uint32_t a;
    asm("{ .reg .u64 t; cvta.to.shared.u64 t, %1; cvt.u32.u64 %0, t; }" : "=r"(a) : "l"(p));
    return a;
}

#define LDSM4(r0, r1, r2, r3, a) \
    asm volatile("ldmatrix.sync.aligned.m8n8.x4.shared.b16 {%0,%1,%2,%3}, [%4];" \
        : "=r"(r0), "=r"(r1), "=r"(r2), "=r"(r3) : "r"(a))

#define MMA(d, A0, A1, A2, A3, B0, B1) \
    asm volatile("mma.sync.aligned.m16n8k16.row.col.f32.bf16.bf16.f32 " \
        "{%0,%1,%2,%3},{%4,%5,%6,%7},{%8,%9},{%0,%1,%2,%3};" \
        : "+f"((d)[0]), "+f"((d)[1]), "+f"((d)[2]), "+f"((d)[3]) \
        : "r"(A0), "r"(A1), "r"(A2), "r"(A3), "r"(B0), "r"(B1))

// ---------------- small kernels ----------------
__global__ void k_init(const float* __restrict__ temp) {
    float sp = log1pf(expf(temp[0]));
    g_it = 1.0f / sp;
    g_negmin_e = 0xFFFFFFFFu; g_negmax_e = 0u;
    g_pvmin_e = 0xFFFFFFFFu;  g_pvmax_e = 0u;
}

__global__ void k_norm(const float* __restrict__ emb) {
    int row = blockIdx.x, t = threadIdx.x;
    float x = emb[row * ND + t];
    float s = x * x;
    #pragma unroll
    for (int o = 16; o > 0; o >>= 1) s += __shfl_xor_sync(0xFFFFFFFFu, s, o);
    __shared__ float ws[8];
    if ((t & 31) == 0) ws[t >> 5] = s;
    __syncthreads();
    float tot = 0.f;
    #pragma unroll
    for (int i = 0; i < 8; i++) tot += ws[i];
    g_zb[row * ND + t] = __float2bfloat16(x / fmaxf(sqrtf(tot), 1e-12f));
}

__global__ void k_pvminmax(const float* __restrict__ pv) {
    int i = blockIdx.x * blockDim.x + threadIdx.x;
    float v = pv[i], mn = v, mx = v;
    #pragma unroll
    for (int o = 16; o > 0; o >>= 1) {
        mn = fminf(mn, __shfl_xor_sync(0xFFFFFFFFu, mn, o));
        mx = fmaxf(mx, __shfl_xor_sync(0xFFFFFFFFu, mx, o));
    }
    if ((threadIdx.x & 31) == 0) { atomicMin(&g_pvmin_e, encf(mn)); atomicMax(&g_pvmax_e, encf(mx)); }
}

// ---------------- fused GEMM (mma.sync bf16 + ldmatrix) + epilogue ----------------
__device__ __forceinline__ void load_panel(uint32_t sdst, const __nv_bfloat16* zrow0, int tid) {
    const char* g = (const char*)zrow0;
    #pragma unroll
    for (int i = 0; i < 16; i++) {
        int seg = tid + i * 256;               // 4096 16B segments
        int row = seg >> 5, c16 = seg & 31;
        CP16(sdst + row * RS + c16 * 16, g + row * 512 + c16 * 16);
    }
}

__global__ void __launch_bounds__(256, 1) k_sim() {
    extern __shared__ __align__(16) char smem[];
    const int tid = threadIdx.x, w = tid >> 5, lane = tid & 31;
    const int bc = blockIdx.x;                 // 0..1 : 4096-col chunk
    const int bm = blockIdx.y;                 // 0..63: 128-row stripe
    const int wr = w & 3, wc = w >> 2;         // 32-row band, 64-col half
    const uint32_t sbase = smem_u32(smem);
    const uint32_t sA = sbase, sB0 = sbase + TILE_B, sB1 = sbase + 2 * TILE_B;

    load_panel(sA, g_zb + (size_t)(bm * 128) * ND, tid);
    load_panel(sB0, g_zb + (size_t)(bc * 4096) * ND, tid);
    CP_COMMIT();
    load_panel(sB1, g_zb + (size_t)(bc * 4096 + 128) * ND, tid);
    CP_COMMIT();

    const float it = g_it;
    const int rowbase = bm * 128 + wr * 32;
    // ldmatrix per-lane base offsets (bytes)
    const uint32_t offA = (uint32_t)(wr * 32 + (lane & 15)) * RS + (uint32_t)(lane >> 4) * 16;
    const uint32_t offB = (uint32_t)(wc * 64 + ((lane >> 4) & 1) * 8 + (lane & 7)) * RS
                        + (uint32_t)((lane >> 3) & 1) * 16;

    float spd[2][2], sng[2][2], tng[2][2];
    #pragma unroll
    for (int a = 0; a < 2; a++)
        #pragma unroll
        for (int b = 0; b < 2; b++) { spd[a][b] = 0.f; sng[a][b] = 0.f; tng[a][b] = 0.f; }
    float mn = 1e30f, mx = -1e30f;

    for (int t = 0; t < 32; t++) {
        if (t < 30) { CP_WAIT(1); } else { CP_WAIT(0); }
        __syncthreads();
        const uint32_t sB = (t & 1) ? sB1 : sB0;

        float acc[2][8][4];
        #pragma unroll
        for (int m = 0; m < 2; m++)
            #pragma unroll
            for (int n = 0; n < 8; n++)
                #pragma unroll
                for (int q = 0; q < 4; q++) acc[m][n][q] = 0.f;

        #pragma unroll
        for (int kk = 0; kk < 16; kk++) {
            uint32_t a0[2], a1[2], a2[2], a3[2];
            #pragma unroll
            for (int m = 0; m < 2; m++)
                LDSM4(a0[m], a1[m], a2[m], a3[m], sA + offA + (uint32_t)m * (16 * RS) + (uint32_t)kk * 32);
            uint32_t b0[8], b1[8];
            #pragma unroll
            for (int p = 0; p < 4; p++)
                LDSM4(b0[2 * p], b1[2 * p], b0[2 * p + 1], b1[2 * p + 1],
                      sB + offB + (uint32_t)p * (16 * RS) + (uint32_t)kk * 32);
            #pragma unroll
            for (int m = 0; m < 2; m++)
                #pragma unroll
                for (int n = 0; n < 8; n++)
                    MMA(acc[m][n], a0[m], a1[m], a2[m], a3[m], b0[n], b1[n]);
        }

        __syncthreads();
        if (t + 2 < 32) {
            load_panel((t & 1) ? sB1 : sB0,
                       g_zb + (size_t)(bc * 4096 + (t + 2) * 128) * ND, tid);
            CP_COMMIT();
        }

        // ---- epilogue on registers ----
        const int colbase = bc * 4096 + t * 128 + wc * 64 + (lane & 3) * 2;
        #pragma unroll
        for (int m = 0; m < 2; m++) {
            #pragma unroll
            for (int n = 0; n < 8; n++) {
                #pragma unroll
                for (int h = 0; h < 2; h++) {
                    int row = rowbase + m * 16 + (lane >> 2) + h * 8;
                    #pragma unroll
                    for (int q = 0; q < 2; q++) {
                        int col = colbase + n * 8 + q;
                        float v = acc[m][n][h * 2 + q];
                        float s = fmaf(v, it, -it);
                        float e = __expf(s);
                        unsigned d = (unsigned)(col - row) & 8191u;
                        if (d == 0u) {
                            spd[m][h] += e;
                        } else if (d <= 8u) {
                            spd[m][h] += e;
                            g_pos_s[row * NPOS + d - 1] = s;
                        } else {
                            sng[m][h] += e;
                            tng[m][h] = fmaf(s, e, tng[m][h]);
                            mn = fminf(mn, s); mx = fmaxf(mx, s);
                        }
                    }
                }
            }
        }
    }

    // reduce the 4 lanes (lane&3) sharing each row
    const int sidx = bc * 2 + wc;
    #pragma unroll
    for (int m = 0; m < 2; m++)
        #pragma unroll
        for (int h = 0; h < 2; h++) {
            float a0 = spd[m][h], a1 = sng[m][h], a2 = tng[m][h];
            a0 += __shfl_down_sync(0xFFFFFFFFu, a0, 2, 4);
            a0 += __shfl_down_sync(0xFFFFFFFFu, a0, 1, 4);
            a1 += __shfl_down_sync(0xFFFFFFFFu, a1, 2, 4);
            a1 += __shfl_down_sync(0xFFFFFFFFu, a1, 1, 4);
            a2 += __shfl_down_sync(0xFFFFFFFFu, a2, 2, 4);
            a2 += __shfl_down_sync(0xFFFFFFFFu, a2, 1, 4);
            if ((lane & 3) == 0) {
                int row = rowbase + m * 16 + (lane >> 2) + h * 8;
                g_pSpd [sidx * NB + row] = a0;
                g_pSneg[sidx * NB + row] = a1;
                g_pTneg[sidx * NB + row] = a2;
            }
        }
    #pragma unroll
    for (int o = 16; o > 0; o >>= 1) {
        mn = fminf(mn, __shfl_xor_sync(0xFFFFFFFFu, mn, o));
        mx = fmaxf(mx, __shfl_xor_sync(0xFFFFFFFFu, mx, o));
    }
    if (lane == 0) { atomicMin(&g_negmin_e, encf(mn)); atomicMax(&g_negmax_e, encf(mx)); }
}

__global__ void k_lse() {
    int i = blockIdx.x * blockDim.x + threadIdx.x;
    float spd = 0.f, sn = 0.f, tn = 0.f;
    #pragma unroll
    for (int t = 0; t < 4; t++) {
        spd += g_pSpd [t * NB + i];
        sn  += g_pSneg[t * NB + i];
        tn  += g_pTneg[t * NB + i];
    }
    float nmin = decf2(g_negmin_e), nmax = decf2(g_negmax_e);
    float a = 1.0f / (nmax - nmin + 1e-8f);
    float b = 1.0f - nmin * a;
    g_lse[i] = logf(spd + a * tn + b * sn);
}

__global__ void k_final(const float* __restrict__ pv, float* __restrict__ out) {
    const int tid = threadIdx.x;
    float vmin = decf2(g_pvmin_e), vmax = decf2(g_pvmax_e);
    float wmin = 1.0f - vmax, wmax = 1.0f - vmin;
    float inv = 1.0f / (wmax - wmin + 1e-8f);
    float local = 0.f;
    for (int idx = tid; idx < NB * NPOS; idx += 1024) {
        float pw = ((1.0f - pv[idx]) - wmin) * inv;
        local += (g_pos_s[idx] - g_lse[idx >> 3]) * pw;
    }
    __shared__ float red[1024];
    red[tid] = local;
    __syncthreads();
    for (int s = 512; s > 0; s >>= 1) {
        if (tid < s) red[tid] += red[tid + s];
        __syncthreads();
    }
    if (tid == 0) out[0] = -red[0] * (1.0f / (float)(NB * NPOS));
}

// ---------------- launch ----------------
extern "C" void kernel_launch(void* const* d_in, const int* in_sizes, int n_in,
                              void* d_out, int out_size) {
    const float* emb  = (const float*)d_in[0];
    const float* pv   = (const float*)d_in[1];
    const float* temp = (const float*)d_in[2];
    float* out = (float*)d_out;

    const int SMEM = 3 * TILE_B;               // 202752 B
    cudaFuncSetAttribute(k_sim, cudaFuncAttributeMaxDynamicSharedMemorySize, SMEM);

    k_init<<<1, 1>>>(temp);
    k_norm<<<NB, ND>>>(emb);
    k_pvminmax<<<(NB * NPOS) / 1024, 1024>>>(pv);
    dim3 grid(2, 64);
    k_sim<<<grid, 256, SMEM>>>();
    k_lse<<<NB / 256, 256>>>();
    k_final<<<1, 1024>>>(pv, out);
}

// round 9
// speedup vs baseline: 4.2723x; 1.3019x over previous
#include <cuda_runtime.h>
#include <cuda_bf16.h>
#include <math.h>
#include <stdint.h>

#define NB 8192
#define ND 256
#define NPOS 8
#define RS 528           // smem row stride bytes (256 bf16 + 8 pad)
#define TILE_B (128 * RS)
#define NTHREADS 512

__device__ __align__(16) __nv_bfloat16 g_zb[NB * ND];
__device__ float g_pSpd[8 * NB], g_pSneg[8 * NB], g_pTneg[8 * NB];
__device__ float g_pos_s[NB * NPOS], g_lse[NB];
__device__ float g_it;
__device__ unsigned g_negmin_e, g_negmax_e, g_pvmin_e, g_pvmax_e;

__device__ __forceinline__ unsigned encf(float f) {
    unsigned u = __float_as_uint(f);
    return (u & 0x80000000u) ? ~u : (u | 0x80000000u);
}
__device__ __forceinline__ float decf2(unsigned e) {
    unsigned u = (e & 0x80000000u) ? (e ^ 0x80000000u) : ~e;
    return __uint_as_float(u);
}

#define CP16(s, g)  asm volatile("cp.async.cg.shared.global [%0], [%1], 16;" :: "r"(s), "l"(g))
#define CP_COMMIT() asm volatile("cp.async.commit_group;" ::: "memory")
#define CP_WAIT(n)  asm volatile("cp.async.wait_group %0;" :: "n"(n) : "memory")

__device__ __forceinline__ uint32_t smem_u32(const void* p) {
    uint32_t a;
    asm("{ .reg .u64 t; cvta.to.shared.u64 t, %1; cvt.u32.u64 %0, t; }" : "=r"(a) : "l"(p));
    return a;
}

#define LDSM4(r0, r1, r2, r3, a) \
    asm volatile("ldmatrix.sync.aligned.m8n8.x4.shared.b16 {%0,%1,%2,%3}, [%4];" \
        : "=r"(r0), "=r"(r1), "=r"(r2), "=r"(r3) : "r"(a))

#define MMA(d, A0, A1, A2, A3, B0, B1) \
    asm volatile("mma.sync.aligned.m16n8k16.row.col.f32.bf16.bf16.f32 " \
        "{%0,%1,%2,%3},{%4,%5,%6,%7},{%8,%9},{%0,%1,%2,%3};" \
        : "+f"((d)[0]), "+f"((d)[1]), "+f"((d)[2]), "+f"((d)[3]) \
        : "r"(A0), "r"(A1), "r"(A2), "r"(A3), "r"(B0), "r"(B1))

// ---------------- small kernels ----------------
__global__ void k_init(const float* __restrict__ temp) {
    float sp = log1pf(expf(temp[0]));
    g_it = 1.0f / sp;
    g_negmin_e = 0xFFFFFFFFu; g_negmax_e = 0u;
    g_pvmin_e = 0xFFFFFFFFu;  g_pvmax_e = 0u;
}

__global__ void k_norm(const float* __restrict__ emb) {
    int row = blockIdx.x, t = threadIdx.x;
    float x = emb[row * ND + t];
    float s = x * x;
    #pragma unroll
    for (int o = 16; o > 0; o >>= 1) s += __shfl_xor_sync(0xFFFFFFFFu, s, o);
    __shared__ float ws[8];
    if ((t & 31) == 0) ws[t >> 5] = s;
    __syncthreads();
    float tot = 0.f;
    #pragma unroll
    for (int i = 0; i < 8; i++) tot += ws[i];
    g_zb[row * ND + t] = __float2bfloat16(x / fmaxf(sqrtf(tot), 1e-12f));
}

__global__ void k_pvminmax(const float* __restrict__ pv) {
    int i = blockIdx.x * blockDim.x + threadIdx.x;
    float v = pv[i], mn = v, mx = v;
    #pragma unroll
    for (int o = 16; o > 0; o >>= 1) {
        mn = fminf(mn, __shfl_xor_sync(0xFFFFFFFFu, mn, o));
        mx = fmaxf(mx, __shfl_xor_sync(0xFFFFFFFFu, mx, o));
    }
    if ((threadIdx.x & 31) == 0) { atomicMin(&g_pvmin_e, encf(mn)); atomicMax(&g_pvmax_e, encf(mx)); }
}

// ---------------- fused GEMM (mma.sync bf16 + ldmatrix) + epilogue ----------------
__device__ __forceinline__ void load_panel(uint32_t sdst, const __nv_bfloat16* zrow0, int tid) {
    const char* g = (const char*)zrow0;
    #pragma unroll
    for (int i = 0; i < 8; i++) {
        int seg = tid + i * NTHREADS;          // 4096 16B segments
        int row = seg >> 5, c16 = seg & 31;
        CP16(sdst + row * RS + c16 * 16, g + row * 512 + c16 * 16);
    }
}

__global__ void __launch_bounds__(NTHREADS, 1) k_sim() {
    extern __shared__ __align__(16) char smem[];
    const int tid = threadIdx.x, w = tid >> 5, lane = tid & 31;
    const int bc = blockIdx.x;                 // 0..1 : 4096-col chunk
    const int bm = blockIdx.y;                 // 0..63: 128-row stripe
    const int wr = w & 3, wc = w >> 2;         // 32-row band, 32-col quarter (0..3)
    const uint32_t sbase = smem_u32(smem);
    const uint32_t sA = sbase, sB0 = sbase + TILE_B, sB1 = sbase + 2 * TILE_B;

    load_panel(sA, g_zb + (size_t)(bm * 128) * ND, tid);
    load_panel(sB0, g_zb + (size_t)(bc * 4096) * ND, tid);
    CP_COMMIT();
    load_panel(sB1, g_zb + (size_t)(bc * 4096 + 128) * ND, tid);
    CP_COMMIT();

    const float it = g_it;
    const int rowbase = bm * 128 + wr * 32;
    const uint32_t offA = (uint32_t)(wr * 32 + (lane & 15)) * RS + (uint32_t)(lane >> 4) * 16;
    const uint32_t offB = (uint32_t)(wc * 32 + ((lane >> 4) & 1) * 8 + (lane & 7)) * RS
                        + (uint32_t)((lane >> 3) & 1) * 16;

    float spd[2][2], sng[2][2], tng[2][2];
    #pragma unroll
    for (int a = 0; a < 2; a++)
        #pragma unroll
        for (int b = 0; b < 2; b++) { spd[a][b] = 0.f; sng[a][b] = 0.f; tng[a][b] = 0.f; }
    float mn = 1e30f, mx = -1e30f;

    for (int t = 0; t < 32; t++) {
        if (t < 30) { CP_WAIT(1); } else { CP_WAIT(0); }
        __syncthreads();
        const uint32_t sB = (t & 1) ? sB1 : sB0;

        float acc[2][4][4];
        #pragma unroll
        for (int m = 0; m < 2; m++)
            #pragma unroll
            for (int n = 0; n < 4; n++)
                #pragma unroll
                for (int q = 0; q < 4; q++) acc[m][n][q] = 0.f;

        #pragma unroll
        for (int kk = 0; kk < 16; kk++) {
            uint32_t a0[2], a1[2], a2[2], a3[2];
            #pragma unroll
            for (int m = 0; m < 2; m++)
                LDSM4(a0[m], a1[m], a2[m], a3[m], sA + offA + (uint32_t)m * (16 * RS) + (uint32_t)kk * 32);
            uint32_t b0[4], b1[4];
            #pragma unroll
            for (int p = 0; p < 2; p++)
                LDSM4(b0[2 * p], b1[2 * p], b0[2 * p + 1], b1[2 * p + 1],
                      sB + offB + (uint32_t)p * (16 * RS) + (uint32_t)kk * 32);
            #pragma unroll
            for (int m = 0; m < 2; m++)
                #pragma unroll
                for (int n = 0; n < 4; n++)
                    MMA(acc[m][n], a0[m], a1[m], a2[m], a3[m], b0[n], b1[n]);
        }

        __syncthreads();
        if (t + 2 < 32) {
            load_panel((t & 1) ? sB1 : sB0,
                       g_zb + (size_t)(bc * 4096 + (t + 2) * 128) * ND, tid);
            CP_COMMIT();
        }

        // ---- epilogue on registers ----
        const int colbase = bc * 4096 + t * 128 + wc * 32 + (lane & 3) * 2;
        #pragma unroll
        for (int m = 0; m < 2; m++) {
            #pragma unroll
            for (int n = 0; n < 4; n++) {
                #pragma unroll
                for (int h = 0; h < 2; h++) {
                    int row = rowbase + m * 16 + (lane >> 2) + h * 8;
                    #pragma unroll
                    for (int q = 0; q < 2; q++) {
                        int col = colbase + n * 8 + q;
                        float v = acc[m][n][h * 2 + q];
                        float s = fmaf(v, it, -it);
                        float e = __expf(s);
                        unsigned d = (unsigned)(col - row) & 8191u;
                        if (d == 0u) {
                            spd[m][h] += e;
                        } else if (d <= 8u) {
                            spd[m][h] += e;
                            g_pos_s[row * NPOS + d - 1] = s;
                        } else {
                            sng[m][h] += e;
                            tng[m][h] = fmaf(s, e, tng[m][h]);
                            mn = fminf(mn, s); mx = fmaxf(mx, s);
                        }
                    }
                }
            }
        }
    }

    // reduce the 4 lanes (lane&3) sharing each row
    const int sidx = bc * 4 + wc;
    #pragma unroll
    for (int m = 0; m < 2; m++)
        #pragma unroll
        for (int h = 0; h < 2; h++) {
            float a0 = spd[m][h], a1 = sng[m][h], a2 = tng[m][h];
            a0 += __shfl_down_sync(0xFFFFFFFFu, a0, 2, 4);
            a0 += __shfl_down_sync(0xFFFFFFFFu, a0, 1, 4);
            a1 += __shfl_down_sync(0xFFFFFFFFu, a1, 2, 4);
            a1 += __shfl_down_sync(0xFFFFFFFFu, a1, 1, 4);
            a2 += __shfl_down_sync(0xFFFFFFFFu, a2, 2, 4);
            a2 += __shfl_down_sync(0xFFFFFFFFu, a2, 1, 4);
            if ((lane & 3) == 0) {
                int row = rowbase + m * 16 + (lane >> 2) + h * 8;
                g_pSpd [sidx * NB + row] = a0;
                g_pSneg[sidx * NB + row] = a1;
                g_pTneg[sidx * NB + row] = a2;
            }
        }
    #pragma unroll
    for (int o = 16; o > 0; o >>= 1) {
        mn = fminf(mn, __shfl_xor_sync(0xFFFFFFFFu, mn, o));
        mx = fmaxf(mx, __shfl_xor_sync(0xFFFFFFFFu, mx, o));
    }
    if (lane == 0) { atomicMin(&g_negmin_e, encf(mn)); atomicMax(&g_negmax_e, encf(mx)); }
}

__global__ void k_lse() {
    int i = blockIdx.x * blockDim.x + threadIdx.x;
    float spd = 0.f, sn = 0.f, tn = 0.f;
    #pragma unroll
    for (int t = 0; t < 8; t++) {
        spd += g_pSpd [t * NB + i];
        sn  += g_pSneg[t * NB + i];
        tn  += g_pTneg[t * NB + i];
    }
    float nmin = decf2(g_negmin_e), nmax = decf2(g_negmax_e);
    float a = 1.0f / (nmax - nmin + 1e-8f);
    float b = 1.0f - nmin * a;
    g_lse[i] = logf(spd + a * tn + b * sn);
}

__global__ void k_final(const float* __restrict__ pv, float* __restrict__ out) {
    const int tid = threadIdx.x;
    float vmin = decf2(g_pvmin_e), vmax = decf2(g_pvmax_e);
    float wmin = 1.0f - vmax, wmax = 1.0f - vmin;
    float inv = 1.0f / (wmax - wmin + 1e-8f);
    float local = 0.f;
    for (int idx = tid; idx < NB * NPOS; idx += 1024) {
        float pw = ((1.0f - pv[idx]) - wmin) * inv;
        local += (g_pos_s[idx] - g_lse[idx >> 3]) * pw;
    }
    __shared__ float red[1024];
    red[tid] = local;
    __syncthreads();
    for (int s = 512; s > 0; s >>= 1) {
        if (tid < s) red[tid] += red[tid + s];
        __syncthreads();
    }
    if (tid == 0) out[0] = -red[0] * (1.0f / (float)(NB * NPOS));
}

// ---------------- launch ----------------
extern "C" void kernel_launch(void* const* d_in, const int* in_sizes, int n_in,
                              void* d_out, int out_size) {
    const float* emb  = (const float*)d_in[0];
    const float* pv   = (const float*)d_in[1];
    const float* temp = (const float*)d_in[2];
    float* out = (float*)d_out;

    const int SMEM = 3 * TILE_B;               // 202752 B
    cudaFuncSetAttribute(k_sim, cudaFuncAttributeMaxDynamicSharedMemorySize, SMEM);

    k_init<<<1, 1>>>(temp);
    k_norm<<<NB, ND>>>(emb);
    k_pvminmax<<<(NB * NPOS) / 1024, 1024>>>(pv);
    dim3 grid(2, 64);
    k_sim<<<grid, NTHREADS, SMEM>>>();
    k_lse<<<NB / 256, 256>>>();
    k_final<<<1, 1024>>>(pv, out);
}